// round 10
// baseline (speedup 1.0000x reference)
#include <cuda_runtime.h>
#include <cuda_bf16.h>
#include <cstdint>
#include <math.h>

#define N 2048
#define NN (N*N)
#define K12 12
#define H1 4
#define NG 8
#define OUTF 10
#define KCH 32
#define LOG2E 1.4426950408889634f

// ---------------- scratch ----------------
__device__ float g_csum[32*N];
__device__ float g_ccnt[32*N];
__device__ float g_mean[N];
__device__ float g_we[8];
__device__ float g_hf1t[N*256];
__device__ float g_hf2t[N*64];
__device__ float g_as[H1*N];
__device__ float g_ad[H1*N];
__device__ float g_part[8*N*256];
__device__ float g_rsum[32*N];
__device__ float g_o1[N*256];
__device__ float g_o2[N*64];

__device__ __forceinline__ float to_tf32(float x) {
    unsigned int u;
    asm("cvt.rna.tf32.f32 %0, %1;" : "=r"(u) : "f"(x));
    return __uint_as_float(u);
}

// ---------------- 1: agg = w.attn + b ; edge = relu ; register-resident column stats ----------------
__global__ void __launch_bounds__(256) k_aggT(const float* __restrict__ attn,
                                              const float* __restrict__ w,
                                              const float* __restrict__ b,
                                              float* __restrict__ edge,
                                              float* __restrict__ csum,
                                              float* __restrict__ ccnt) {
    __shared__ float rs[16][64], rc[16][64];
    int bx = blockIdx.x * 64, by = blockIdx.y * 64;
    int tid = threadIdx.x;
    int tx = tid & 15, ty = tid >> 4;
    float wv[K12];
#pragma unroll
    for (int k = 0; k < K12; k++) wv[k] = w[k];
    float bb = b[0];
    float cs[4] = {0.f, 0.f, 0.f, 0.f}, cc[4] = {0.f, 0.f, 0.f, 0.f};
#pragma unroll
    for (int rr = 0; rr < 4; rr++) {
        int row = rr * 16 + ty;
        float4 acc = make_float4(bb, bb, bb, bb);
#pragma unroll
        for (int k = 0; k < K12; k++) {
            float4 v = *(const float4*)(attn + (size_t)k * NN + (size_t)(by + row) * N + bx + tx * 4);
            acc.x += wv[k] * v.x; acc.y += wv[k] * v.y;
            acc.z += wv[k] * v.z; acc.w += wv[k] * v.w;
        }
        acc.x = acc.x > 0.f ? acc.x : 0.f;
        acc.y = acc.y > 0.f ? acc.y : 0.f;
        acc.z = acc.z > 0.f ? acc.z : 0.f;
        acc.w = acc.w > 0.f ? acc.w : 0.f;
        *(float4*)(edge + (size_t)(by + row) * N + bx + tx * 4) = acc;
        int grow = by + row;
        float av[4] = {acc.x, acc.y, acc.z, acc.w};
#pragma unroll
        for (int q = 0; q < 4; q++) {
            if (av[q] > 0.f && grow != bx + tx * 4 + q) { cs[q] += av[q]; cc[q] += 1.f; }
        }
    }
    *(float4*)&rs[ty][tx * 4] = make_float4(cs[0], cs[1], cs[2], cs[3]);
    *(float4*)&rc[ty][tx * 4] = make_float4(cc[0], cc[1], cc[2], cc[3]);
    __syncthreads();
    if (tid < 64) {
        float s = 0.f, c = 0.f;
#pragma unroll
        for (int g = 0; g < 16; g++) { s += rs[g][tid]; c += rc[g][tid]; }
        csum[blockIdx.y * N + bx + tid] = s;
        ccnt[blockIdx.y * N + bx + tid] = c;
    }
}

// ---------------- 2: means + per-head edge weights ----------------
__global__ void k_mean(const float* __restrict__ cs, const float* __restrict__ cc,
                       float* __restrict__ mean,
                       const float* __restrict__ We1, const float* __restrict__ ae1,
                       const float* __restrict__ We2, const float* __restrict__ ae2,
                       float* __restrict__ we) {
    int j = blockIdx.x * 256 + threadIdx.x;
    if (j < N) {
        float s = 0.f, c = 0.f;
        for (int b2 = 0; b2 < 32; b2++) { s += cs[b2 * N + j]; c += cc[b2 * N + j]; }
        mean[j] = c > 0.f ? s / c : 0.f;
    }
    if (blockIdx.x == 8) {
        int t = threadIdx.x;
        if (t < 4) {
            float s = 0.f;
            for (int c = 0; c < 64; c++) s += We1[t * 64 + c] * ae1[t * 64 + c];
            we[t] = s;
        } else if (t == 4) {
            float s = 0.f;
            for (int c = 0; c < 64; c++) s += We2[c] * ae2[c];
            we[4] = s;
        }
    }
}

// ---------------- feature GEMM + attention-dot epilogue + tf32 output ----------------
template<int TM>
__global__ void __launch_bounds__(256) k_gemm(const float* __restrict__ A,
        const float* __restrict__ B, float* __restrict__ Ct, int K, int ldb, int ldn,
        const float* __restrict__ asrc, const float* __restrict__ adst,
        float* __restrict__ oas, float* __restrict__ oad) {
    constexpr int R = TM / 16;
    __shared__ float As2[16][TM + 1];
    __shared__ float Bs2[16][64];
    int h = blockIdx.y;
    int m0 = blockIdx.x * TM, n0 = h * 64;
    int tid = threadIdx.x;
    int tx = tid & 15, ty = tid >> 4;
    float acc[R][4];
#pragma unroll
    for (int r = 0; r < R; r++)
#pragma unroll
        for (int c = 0; c < 4; c++) acc[r][c] = 0.f;
    for (int k0 = 0; k0 < K; k0 += 16) {
#pragma unroll
        for (int l = 0; l < R; l++) {
            int e = l * 256 + tid;
            As2[e & 15][e >> 4] = A[(size_t)(m0 + (e >> 4)) * K + k0 + (e & 15)];
        }
#pragma unroll
        for (int l = 0; l < 4; l++) {
            int e = l * 256 + tid;
            Bs2[e >> 6][e & 63] = B[(size_t)(k0 + (e >> 6)) * ldb + n0 + (e & 63)];
        }
        __syncthreads();
#pragma unroll
        for (int kk = 0; kk < 16; kk++) {
            float a[R], bb[4];
#pragma unroll
            for (int r = 0; r < R; r++) a[r] = As2[kk][ty * R + r];
#pragma unroll
            for (int c = 0; c < 4; c++) bb[c] = Bs2[kk][tx * 4 + c];
#pragma unroll
            for (int r = 0; r < R; r++)
#pragma unroll
                for (int c = 0; c < 4; c++) acc[r][c] += a[r] * bb[c];
        }
        __syncthreads();
    }
    int lane = tid & 31;
    float asv[4], adv[4];
#pragma unroll
    for (int c = 0; c < 4; c++) {
        asv[c] = asrc[h * 64 + tx * 4 + c];
        adv[c] = adst[h * 64 + tx * 4 + c];
    }
#pragma unroll
    for (int r = 0; r < R; r++) {
        int row = m0 + ty * R + r;
        float ds = 0.f, dd = 0.f;
#pragma unroll
        for (int c = 0; c < 4; c++) {
            float v = acc[r][c];
            Ct[(size_t)row * ldn + n0 + tx * 4 + c] = to_tf32(v);
            ds += v * asv[c];
            dd += v * adv[c];
        }
#pragma unroll
        for (int m = 1; m < 16; m <<= 1) {
            ds += __shfl_xor_sync(0xffffffffu, ds, m);
            dd += __shfl_xor_sync(0xffffffffu, dd, m);
        }
        if ((lane & 15) == 0) { oas[h * N + row] = ds; oad[h * N + row] = dd; }
    }
}

// ---------------- fused logits + softmax + tf32 MMA (single-buffer, 3 CTAs/SM) ----------------
template<int H, int S>
__global__ void __launch_bounds__(256, 3) k_fattn(const float* __restrict__ edge,
        const float* __restrict__ mean, const float* __restrict__ as_,
        const float* __restrict__ ad_, const float* __restrict__ wep, int woff,
        const float* __restrict__ Bf, float* __restrict__ part, float* __restrict__ rsum) {
    constexpr int KR = N / S;
    constexpr int CH = KR / KCH;
    const int ldn = H * 64;
    __shared__ float AsT[KCH][136];
    __shared__ float Bs[KCH][72];
    __shared__ float s_as[KR];
    __shared__ float rred[8][32][4];
    int tid = threadIdx.x;
    int h = blockIdx.x, m0 = blockIdx.y * 128, s = blockIdx.z;
    int kb = s * KR;
    for (int idx = tid; idx < KR; idx += 256) s_as[idx] = as_[h * N + kb + idx] * LOG2E;
    int jq = tid & 31, ig = tid >> 5;
    float adj[4], me[4];
#pragma unroll
    for (int q = 0; q < 4; q++) {
        adj[q] = ad_[h * N + m0 + jq * 4 + q] * LOG2E;
        me[q]  = mean[m0 + jq * 4 + q];
    }
    float wev = wep[woff + h] * LOG2E;
    int brow = tid >> 3, bc8 = tid & 7;
    int wid = tid >> 5, lane = tid & 31;
    int wm = wid >> 1, wn = wid & 1, gid = lane >> 2, tig = lane & 3;
    float acc[2][4][4];
#pragma unroll
    for (int mt = 0; mt < 2; mt++)
#pragma unroll
        for (int nt = 0; nt < 4; nt++)
#pragma unroll
            for (int q = 0; q < 4; q++) acc[mt][nt][q] = 0.f;
    float racc[4] = {0.f, 0.f, 0.f, 0.f};
    float4 ev4[4];
    float4 bv0, bv1;
#pragma unroll
    for (int b = 0; b < 4; b++)
        ev4[b] = *(const float4*)(edge + (size_t)(kb + ig + 8 * b) * N + m0 + jq * 4);
    bv0 = *(const float4*)(Bf + (size_t)(kb + brow) * ldn + h * 64 + bc8 * 8);
    bv1 = *(const float4*)(Bf + (size_t)(kb + brow) * ldn + h * 64 + bc8 * 8 + 4);
    __syncthreads();   // s_as ready

    for (int c = 0; c < CH; c++) {
        int kc = kb + c * KCH;
#pragma unroll
        for (int b = 0; b < 4; b++) {
            int il = ig + 8 * b;
            int srcg = kc + il;
            float p4[4];
            float evq[4] = {ev4[b].x, ev4[b].y, ev4[b].z, ev4[b].w};
            float sa = s_as[c * KCH + il];
#pragma unroll
            for (int q = 0; q < 4; q++) {
                bool diag = (srcg == m0 + jq * 4 + q);
                float e = diag ? me[q] : evq[q];
                bool on = diag || (evq[q] > 0.f);
                float v = sa + adj[q] + e * wev;
                v = fmaxf(v, 0.2f * v);
                float p;
                asm("ex2.approx.f32 %0, %1;" : "=f"(p) : "f"(v));
                p = on ? to_tf32(p) : 0.f;
                p4[q] = p;
                racc[q] += p;
            }
            *(float4*)&AsT[il][jq * 4] = make_float4(p4[0], p4[1], p4[2], p4[3]);
        }
        *(float4*)&Bs[brow][bc8 * 8]     = bv0;
        *(float4*)&Bs[brow][bc8 * 8 + 4] = bv1;
        if (c + 1 < CH) {   // prefetch next chunk (issue early, consume after sync2)
            int kn = kc + KCH;
#pragma unroll
            for (int b = 0; b < 4; b++)
                ev4[b] = *(const float4*)(edge + (size_t)(kn + ig + 8 * b) * N + m0 + jq * 4);
            bv0 = *(const float4*)(Bf + (size_t)(kn + brow) * ldn + h * 64 + bc8 * 8);
            bv1 = *(const float4*)(Bf + (size_t)(kn + brow) * ldn + h * 64 + bc8 * 8 + 4);
        }
        __syncthreads();   // P/B tiles visible
#pragma unroll
        for (int kk = 0; kk < 4; kk++) {
            float a[2][4], bq[4][2];
#pragma unroll
            for (int mt = 0; mt < 2; mt++) {
                int r0 = wm * 32 + mt * 16 + gid;
                a[mt][0] = AsT[kk * 8 + tig][r0];
                a[mt][1] = AsT[kk * 8 + tig][r0 + 8];
                a[mt][2] = AsT[kk * 8 + tig + 4][r0];
                a[mt][3] = AsT[kk * 8 + tig + 4][r0 + 8];
            }
#pragma unroll
            for (int nt = 0; nt < 4; nt++) {
                int c0 = wn * 32 + nt * 8 + gid;
                bq[nt][0] = Bs[kk * 8 + tig][c0];
                bq[nt][1] = Bs[kk * 8 + tig + 4][c0];
            }
#pragma unroll
            for (int mt = 0; mt < 2; mt++)
#pragma unroll
                for (int nt = 0; nt < 4; nt++)
                    asm volatile("mma.sync.aligned.m16n8k8.row.col.f32.tf32.tf32.f32 "
                                 "{%0,%1,%2,%3}, {%4,%5,%6,%7}, {%8,%9}, {%0,%1,%2,%3};"
                                 : "+f"(acc[mt][nt][0]), "+f"(acc[mt][nt][1]),
                                   "+f"(acc[mt][nt][2]), "+f"(acc[mt][nt][3])
                                 : "r"(__float_as_uint(a[mt][0])), "r"(__float_as_uint(a[mt][1])),
                                   "r"(__float_as_uint(a[mt][2])), "r"(__float_as_uint(a[mt][3])),
                                   "r"(__float_as_uint(bq[nt][0])), "r"(__float_as_uint(bq[nt][1])));
        }
        __syncthreads();   // reads done before next chunk's stores
    }

    *(float4*)&rred[ig][jq][0] = make_float4(racc[0], racc[1], racc[2], racc[3]);
    __syncthreads();
    if (tid < 128) {
        float ssum = 0.f;
#pragma unroll
        for (int g = 0; g < 8; g++) ssum += rred[g][tid >> 2][tid & 3];
        rsum[((size_t)s * H + h) * N + m0 + tid] = ssum;
    }
#pragma unroll
    for (int mt = 0; mt < 2; mt++)
#pragma unroll
        for (int nt = 0; nt < 4; nt++) {
            int c0 = wn * 32 + nt * 8 + tig * 2;
#pragma unroll
            for (int pr = 0; pr < 2; pr++) {
                int r = m0 + wm * 32 + mt * 16 + gid + pr * 8;
                *(float2*)&part[((size_t)s * N + r) * ldn + h * 64 + c0] =
                    make_float2(acc[mt][nt][2 * pr + 0], acc[mt][nt][2 * pr + 1]);
            }
        }
}

// ---------------- combine splits: normalize + bias + ELU ----------------
template<int S, int HH>
__global__ void k_comb(const float* __restrict__ part, const float* __restrict__ rsum,
                       const float* __restrict__ bias, float* __restrict__ out) {
    const int ldn = HH * 64;
    int idx = blockIdx.x * 256 + threadIdx.x;
    if (idx >= N * ldn) return;
    int n = idx / ldn, hc = idx % ldn, h = hc >> 6;
    float cs = 0.f, rs = 0.f;
#pragma unroll
    for (int s = 0; s < S; s++) {
        cs += part[((size_t)s * N + n) * ldn + hc];
        rs += rsum[((size_t)s * HH + h) * N + n];
    }
    float v = cs / rs + bias[hc];
    out[idx] = v > 0.f ? v : (expf(v) - 1.f);
}

// ---------------- segment-mean pool + final linear ----------------
__global__ void k_pool(const float* __restrict__ o2, const int* __restrict__ batch,
                       const float* __restrict__ Wl, const float* __restrict__ bl,
                       float* __restrict__ out) {
    int g = blockIdx.x;
    __shared__ float acc[4][64];
    __shared__ float cnts[4];
    int tid = threadIdx.x, q = tid >> 6, c = tid & 63;
    float s = 0.f, cn = 0.f;
    for (int n = q; n < N; n += 4) {
        if (batch[n] == g) { s += o2[(size_t)n * 64 + c]; cn += 1.f; }
    }
    acc[q][c] = s;
    if (c == 0) cnts[q] = cn;
    __syncthreads();
    if (q == 0) {
        float tot = acc[0][c] + acc[1][c] + acc[2][c] + acc[3][c];
        float cc = cnts[0] + cnts[1] + cnts[2] + cnts[3];
        acc[0][c] = tot / fmaxf(cc, 1.f);
    }
    __syncthreads();
    if (tid < OUTF) {
        float s2 = bl[tid];
        for (int c2 = 0; c2 < 64; c2++) s2 += acc[0][c2] * Wl[c2 * OUTF + tid];
        out[g * OUTF + tid] = s2;
    }
}

// ---------------- host ----------------
extern "C" void kernel_launch(void* const* d_in, const int* in_sizes, int n_in,
                              void* d_out, int out_size) {
    const float* x        = (const float*)d_in[0];
    const float* attn     = (const float*)d_in[1];
    const int*   batch    = (const int*)d_in[2];
    const float* w_agg    = (const float*)d_in[3];
    const float* b_agg    = (const float*)d_in[4];
    const float* W1       = (const float*)d_in[5];
    const float* att_src1 = (const float*)d_in[6];
    const float* att_dst1 = (const float*)d_in[7];
    const float* We1      = (const float*)d_in[8];
    const float* att_e1   = (const float*)d_in[9];
    const float* bias1    = (const float*)d_in[10];
    const float* W2       = (const float*)d_in[11];
    const float* att_src2 = (const float*)d_in[12];
    const float* att_dst2 = (const float*)d_in[13];
    const float* We2      = (const float*)d_in[14];
    const float* att_e2   = (const float*)d_in[15];
    const float* bias2    = (const float*)d_in[16];
    const float* W_lin    = (const float*)d_in[17];
    const float* b_lin    = (const float*)d_in[18];

    float* out  = (float*)d_out;
    float* edge = out + (out_size - NN);

    float *csum, *ccnt, *meanp, *wep, *hf1t, *hf2t, *asp, *adp, *partp, *rsump, *o1p, *o2p;
    cudaGetSymbolAddress((void**)&csum,  g_csum);
    cudaGetSymbolAddress((void**)&ccnt,  g_ccnt);
    cudaGetSymbolAddress((void**)&meanp, g_mean);
    cudaGetSymbolAddress((void**)&wep,   g_we);
    cudaGetSymbolAddress((void**)&hf1t,  g_hf1t);
    cudaGetSymbolAddress((void**)&hf2t,  g_hf2t);
    cudaGetSymbolAddress((void**)&asp,   g_as);
    cudaGetSymbolAddress((void**)&adp,   g_ad);
    cudaGetSymbolAddress((void**)&partp, g_part);
    cudaGetSymbolAddress((void**)&rsump, g_rsum);
    cudaGetSymbolAddress((void**)&o1p,   g_o1);
    cudaGetSymbolAddress((void**)&o2p,   g_o2);

    // edge + column stats (fused)
    k_aggT<<<dim3(32, 32), 256>>>(attn, w_agg, b_agg, edge, csum, ccnt);
    // features layer1 + attention dots (independent of aggT)
    k_gemm<64><<<dim3(32, 4), 256>>>(x, W1, hf1t, 128, 256, 256,
                                     att_src1, att_dst1, asp, adp);
    // means + edge-weight scalars
    k_mean<<<9, 256>>>(csum, ccnt, meanp, We1, att_e1, We2, att_e2, wep);

    // ---- GAT layer 1 (H=4, S=8, 128-dst tiles, h-major grid) ----
    k_fattn<4, 8><<<dim3(4, 16, 8), 256>>>(edge, meanp, asp, adp, wep, 0, hf1t, partp, rsump);
    k_comb<8, 4><<<N * 256 / 256, 256>>>(partp, rsump, bias1, o1p);

    // ---- GAT layer 2 (H=1, S=16) ----
    k_gemm<32><<<dim3(64, 1), 256>>>(o1p, W2, hf2t, 256, 64, 64,
                                     att_src2, att_dst2, asp, adp);
    k_fattn<1, 16><<<dim3(1, 16, 16), 256>>>(edge, meanp, asp, adp, wep, 4, hf2t, partp, rsump);
    k_comb<16, 1><<<N * 64 / 256, 256>>>(partp, rsump, bias2, o2p);

    // ---- pool + final linear ----
    k_pool<<<NG, 256>>>(o2p, batch, W_lin, b_lin, out);
}

// round 11
// speedup vs baseline: 1.0261x; 1.0261x over previous
#include <cuda_runtime.h>
#include <cuda_bf16.h>
#include <cstdint>
#include <math.h>

#define N 2048
#define NN (N*N)
#define K12 12
#define H1 4
#define NG 8
#define OUTF 10
#define KCH 32
#define LOG2E 1.4426950408889634f

// ---------------- scratch ----------------
__device__ float g_csum[32*N];
__device__ float g_ccnt[32*N];
__device__ float g_mean[N];
__device__ float g_we[8];
__device__ float g_hf1t[N*256];
__device__ float g_hf2t[N*64];
__device__ float g_as[H1*N];
__device__ float g_ad[H1*N];
__device__ float g_part[8*N*256];
__device__ float g_rsum[32*N];
__device__ float g_o1[N*256];
__device__ float g_o2[N*64];

__device__ __forceinline__ float to_tf32(float x) {
    unsigned int u;
    asm("cvt.rna.tf32.f32 %0, %1;" : "=r"(u) : "f"(x));
    return __uint_as_float(u);
}
__device__ __forceinline__ void cp16(unsigned int saddr, const void* g) {
    asm volatile("cp.async.ca.shared.global [%0], [%1], 16;" :: "r"(saddr), "l"(g));
}

// ---------------- 1: agg = w.attn + b ; edge = relu ; register-resident column stats ----------------
__global__ void __launch_bounds__(256) k_aggT(const float* __restrict__ attn,
                                              const float* __restrict__ w,
                                              const float* __restrict__ b,
                                              float* __restrict__ edge,
                                              float* __restrict__ csum,
                                              float* __restrict__ ccnt) {
    __shared__ float rs[16][64], rc[16][64];
    int bx = blockIdx.x * 64, by = blockIdx.y * 64;
    int tid = threadIdx.x;
    int tx = tid & 15, ty = tid >> 4;
    float wv[K12];
#pragma unroll
    for (int k = 0; k < K12; k++) wv[k] = w[k];
    float bb = b[0];
    float cs[4] = {0.f, 0.f, 0.f, 0.f}, cc[4] = {0.f, 0.f, 0.f, 0.f};
#pragma unroll
    for (int rr = 0; rr < 4; rr++) {
        int row = rr * 16 + ty;
        float4 acc = make_float4(bb, bb, bb, bb);
#pragma unroll
        for (int k = 0; k < K12; k++) {
            float4 v = *(const float4*)(attn + (size_t)k * NN + (size_t)(by + row) * N + bx + tx * 4);
            acc.x += wv[k] * v.x; acc.y += wv[k] * v.y;
            acc.z += wv[k] * v.z; acc.w += wv[k] * v.w;
        }
        acc.x = acc.x > 0.f ? acc.x : 0.f;
        acc.y = acc.y > 0.f ? acc.y : 0.f;
        acc.z = acc.z > 0.f ? acc.z : 0.f;
        acc.w = acc.w > 0.f ? acc.w : 0.f;
        *(float4*)(edge + (size_t)(by + row) * N + bx + tx * 4) = acc;
        int grow = by + row;
        float av[4] = {acc.x, acc.y, acc.z, acc.w};
#pragma unroll
        for (int q = 0; q < 4; q++) {
            if (av[q] > 0.f && grow != bx + tx * 4 + q) { cs[q] += av[q]; cc[q] += 1.f; }
        }
    }
    *(float4*)&rs[ty][tx * 4] = make_float4(cs[0], cs[1], cs[2], cs[3]);
    *(float4*)&rc[ty][tx * 4] = make_float4(cc[0], cc[1], cc[2], cc[3]);
    __syncthreads();
    if (tid < 64) {
        float s = 0.f, c = 0.f;
#pragma unroll
        for (int g = 0; g < 16; g++) { s += rs[g][tid]; c += rc[g][tid]; }
        csum[blockIdx.y * N + bx + tid] = s;
        ccnt[blockIdx.y * N + bx + tid] = c;
    }
}

// ---------------- 2: means + per-head edge weights ----------------
__global__ void k_mean(const float* __restrict__ cs, const float* __restrict__ cc,
                       float* __restrict__ mean,
                       const float* __restrict__ We1, const float* __restrict__ ae1,
                       const float* __restrict__ We2, const float* __restrict__ ae2,
                       float* __restrict__ we) {
    int j = blockIdx.x * 256 + threadIdx.x;
    if (j < N) {
        float s = 0.f, c = 0.f;
        for (int b2 = 0; b2 < 32; b2++) { s += cs[b2 * N + j]; c += cc[b2 * N + j]; }
        mean[j] = c > 0.f ? s / c : 0.f;
    }
    if (blockIdx.x == 8) {
        int t = threadIdx.x;
        if (t < 4) {
            float s = 0.f;
            for (int c = 0; c < 64; c++) s += We1[t * 64 + c] * ae1[t * 64 + c];
            we[t] = s;
        } else if (t == 4) {
            float s = 0.f;
            for (int c = 0; c < 64; c++) s += We2[c] * ae2[c];
            we[4] = s;
        }
    }
}

// ---------------- feature GEMM + attention-dot epilogue + tf32 output ----------------
template<int TM>
__global__ void __launch_bounds__(256) k_gemm(const float* __restrict__ A,
        const float* __restrict__ B, float* __restrict__ Ct, int K, int ldb, int ldn,
        const float* __restrict__ asrc, const float* __restrict__ adst,
        float* __restrict__ oas, float* __restrict__ oad) {
    constexpr int R = TM / 16;
    __shared__ float As2[16][TM + 1];
    __shared__ float Bs2[16][64];
    int h = blockIdx.y;
    int m0 = blockIdx.x * TM, n0 = h * 64;
    int tid = threadIdx.x;
    int tx = tid & 15, ty = tid >> 4;
    float acc[R][4];
#pragma unroll
    for (int r = 0; r < R; r++)
#pragma unroll
        for (int c = 0; c < 4; c++) acc[r][c] = 0.f;
    for (int k0 = 0; k0 < K; k0 += 16) {
#pragma unroll
        for (int l = 0; l < R; l++) {
            int e = l * 256 + tid;
            As2[e & 15][e >> 4] = A[(size_t)(m0 + (e >> 4)) * K + k0 + (e & 15)];
        }
#pragma unroll
        for (int l = 0; l < 4; l++) {
            int e = l * 256 + tid;
            Bs2[e >> 6][e & 63] = B[(size_t)(k0 + (e >> 6)) * ldb + n0 + (e & 63)];
        }
        __syncthreads();
#pragma unroll
        for (int kk = 0; kk < 16; kk++) {
            float a[R], bb[4];
#pragma unroll
            for (int r = 0; r < R; r++) a[r] = As2[kk][ty * R + r];
#pragma unroll
            for (int c = 0; c < 4; c++) bb[c] = Bs2[kk][tx * 4 + c];
#pragma unroll
            for (int r = 0; r < R; r++)
#pragma unroll
                for (int c = 0; c < 4; c++) acc[r][c] += a[r] * bb[c];
        }
        __syncthreads();
    }
    int lane = tid & 31;
    float asv[4], adv[4];
#pragma unroll
    for (int c = 0; c < 4; c++) {
        asv[c] = asrc[h * 64 + tx * 4 + c];
        adv[c] = adst[h * 64 + tx * 4 + c];
    }
#pragma unroll
    for (int r = 0; r < R; r++) {
        int row = m0 + ty * R + r;
        float ds = 0.f, dd = 0.f;
#pragma unroll
        for (int c = 0; c < 4; c++) {
            float v = acc[r][c];
            Ct[(size_t)row * ldn + n0 + tx * 4 + c] = to_tf32(v);
            ds += v * asv[c];
            dd += v * adv[c];
        }
#pragma unroll
        for (int m = 1; m < 16; m <<= 1) {
            ds += __shfl_xor_sync(0xffffffffu, ds, m);
            dd += __shfl_xor_sync(0xffffffffu, dd, m);
        }
        if ((lane & 15) == 0) { oas[h * N + row] = ds; oad[h * N + row] = dd; }
    }
}

// ---------------- fused logits + softmax + tf32 MMA (cp.async edge pipeline, 2-chunk lookahead) ----------------
template<int H, int S>
__global__ void __launch_bounds__(256, 2) k_fattn(const float* __restrict__ edge,
        const float* __restrict__ mean, const float* __restrict__ as_,
        const float* __restrict__ ad_, const float* __restrict__ wep, int woff,
        const float* __restrict__ Bf, float* __restrict__ part, float* __restrict__ rsum) {
    constexpr int KR = N / S;
    constexpr int CH = KR / KCH;
    const int ldn = H * 64;
    extern __shared__ float dsm[];
    float* AsT  = dsm;                       // [2][32][136]
    float* Bs   = AsT + 2 * 32 * 136;        // [2][32][72]
    float* Es   = Bs + 2 * 32 * 72;          // [3][32][128]
    float* s_as = Es + 3 * 32 * 128;         // [KR]
    float* rred = s_as + KR;                 // [8][32][4]
    unsigned int es_base = (unsigned int)__cvta_generic_to_shared(Es);

    int tid = threadIdx.x;
    int h = blockIdx.x, m0 = blockIdx.y * 128, s = blockIdx.z;
    int kb = s * KR;
    int jq = tid & 31, ig = tid >> 5;

    // issue edge cp.async for chunks 0 and 1
#pragma unroll
    for (int c0 = 0; c0 < 2; c0++) {
#pragma unroll
        for (int b = 0; b < 4; b++) {
            int il = ig + 8 * b;
            cp16(es_base + (((unsigned)(c0 * 32 + il)) * 128 + jq * 4) * 4,
                 edge + (size_t)(kb + c0 * KCH + il) * N + m0 + jq * 4);
        }
        asm volatile("cp.async.commit_group;");
    }

    for (int idx = tid; idx < KR; idx += 256) s_as[idx] = as_[h * N + kb + idx] * LOG2E;
    float adj[4], me[4];
#pragma unroll
    for (int q = 0; q < 4; q++) {
        adj[q] = ad_[h * N + m0 + jq * 4 + q] * LOG2E;
        me[q]  = mean[m0 + jq * 4 + q];
    }
    float wev = wep[woff + h] * LOG2E;
    int brow = tid >> 3, bc8 = tid & 7;
    int wid = tid >> 5, lane = tid & 31;
    int wm = wid >> 1, wn = wid & 1, gid = lane >> 2, tig = lane & 3;
    float acc[2][4][4];
#pragma unroll
    for (int mt = 0; mt < 2; mt++)
#pragma unroll
        for (int nt = 0; nt < 4; nt++)
#pragma unroll
            for (int q = 0; q < 4; q++) acc[mt][nt][q] = 0.f;
    float racc[4] = {0.f, 0.f, 0.f, 0.f};
    float4 bv0, bv1;
    bv0 = *(const float4*)(Bf + (size_t)(kb + brow) * ldn + h * 64 + bc8 * 8);
    bv1 = *(const float4*)(Bf + (size_t)(kb + brow) * ldn + h * 64 + bc8 * 8 + 4);
    __syncthreads();   // s_as ready

    int st = 0, buf = 0;
    for (int c = 0; c < CH; c++) {
        int kc = kb + c * KCH;
        // wait: groups <= c complete (group c+1 may pend)
        asm volatile("cp.async.wait_group 1;");
#pragma unroll
        for (int b = 0; b < 4; b++) {
            int il = ig + 8 * b;
            int srcg = kc + il;
            float4 e4 = *(float4*)(Es + ((st * 32 + il) * 128) + jq * 4);
            float evq[4] = {e4.x, e4.y, e4.z, e4.w};
            float p4[4];
            float sa = s_as[c * KCH + il];
#pragma unroll
            for (int q = 0; q < 4; q++) {
                bool diag = (srcg == m0 + jq * 4 + q);
                float e = diag ? me[q] : evq[q];
                bool on = diag || (evq[q] > 0.f);
                float v = sa + adj[q] + e * wev;
                v = fmaxf(v, 0.2f * v);
                float p;
                asm("ex2.approx.f32 %0, %1;" : "=f"(p) : "f"(v));
                p = on ? to_tf32(p) : 0.f;
                p4[q] = p;
                racc[q] += p;
            }
            *(float4*)&AsT[(buf * 32 + il) * 136 + jq * 4] = make_float4(p4[0], p4[1], p4[2], p4[3]);
        }
        *(float4*)&Bs[(buf * 32 + brow) * 72 + bc8 * 8]     = bv0;
        *(float4*)&Bs[(buf * 32 + brow) * 72 + bc8 * 8 + 4] = bv1;
        // issue edge for chunk c+2 (or empty group to keep accounting constant)
        if (c + 2 < CH) {
            int st2 = st + 2; if (st2 >= 3) st2 -= 3;
            int kn2 = kc + 2 * KCH;
#pragma unroll
            for (int b = 0; b < 4; b++) {
                int il = ig + 8 * b;
                cp16(es_base + (((unsigned)(st2 * 32 + il)) * 128 + jq * 4) * 4,
                     edge + (size_t)(kn2 + il) * N + m0 + jq * 4);
            }
        }
        asm volatile("cp.async.commit_group;");
        if (c + 1 < CH) {
            int kn = kc + KCH;
            bv0 = *(const float4*)(Bf + (size_t)(kn + brow) * ldn + h * 64 + bc8 * 8);
            bv1 = *(const float4*)(Bf + (size_t)(kn + brow) * ldn + h * 64 + bc8 * 8 + 4);
        }
        __syncthreads();   // P/B tiles visible (double-buffered: one sync per chunk)
#pragma unroll
        for (int kk = 0; kk < 4; kk++) {
            float a[2][4], bq[4][2];
#pragma unroll
            for (int mt = 0; mt < 2; mt++) {
                int r0 = wm * 32 + mt * 16 + gid;
                a[mt][0] = AsT[(buf * 32 + kk * 8 + tig) * 136 + r0];
                a[mt][1] = AsT[(buf * 32 + kk * 8 + tig) * 136 + r0 + 8];
                a[mt][2] = AsT[(buf * 32 + kk * 8 + tig + 4) * 136 + r0];
                a[mt][3] = AsT[(buf * 32 + kk * 8 + tig + 4) * 136 + r0 + 8];
            }
#pragma unroll
            for (int nt = 0; nt < 4; nt++) {
                int c0 = wn * 32 + nt * 8 + gid;
                bq[nt][0] = Bs[(buf * 32 + kk * 8 + tig) * 72 + c0];
                bq[nt][1] = Bs[(buf * 32 + kk * 8 + tig + 4) * 72 + c0];
            }
#pragma unroll
            for (int mt = 0; mt < 2; mt++)
#pragma unroll
                for (int nt = 0; nt < 4; nt++)
                    asm volatile("mma.sync.aligned.m16n8k8.row.col.f32.tf32.tf32.f32 "
                                 "{%0,%1,%2,%3}, {%4,%5,%6,%7}, {%8,%9}, {%0,%1,%2,%3};"
                                 : "+f"(acc[mt][nt][0]), "+f"(acc[mt][nt][1]),
                                   "+f"(acc[mt][nt][2]), "+f"(acc[mt][nt][3])
                                 : "r"(__float_as_uint(a[mt][0])), "r"(__float_as_uint(a[mt][1])),
                                   "r"(__float_as_uint(a[mt][2])), "r"(__float_as_uint(a[mt][3])),
                                   "r"(__float_as_uint(bq[nt][0])), "r"(__float_as_uint(bq[nt][1])));
        }
        st = (st + 1 == 3) ? 0 : st + 1;
        buf ^= 1;
    }

    *(float4*)&rred[(ig * 32 + jq) * 4] = make_float4(racc[0], racc[1], racc[2], racc[3]);
    __syncthreads();
    if (tid < 128) {
        float ssum = 0.f;
#pragma unroll
        for (int g = 0; g < 8; g++) ssum += rred[(g * 32 + (tid >> 2)) * 4 + (tid & 3)];
        rsum[((size_t)s * H + h) * N + m0 + tid] = ssum;
    }
#pragma unroll
    for (int mt = 0; mt < 2; mt++)
#pragma unroll
        for (int nt = 0; nt < 4; nt++) {
            int c0 = wn * 32 + nt * 8 + tig * 2;
#pragma unroll
            for (int pr = 0; pr < 2; pr++) {
                int r = m0 + wm * 32 + mt * 16 + gid + pr * 8;
                *(float2*)&part[((size_t)s * N + r) * ldn + h * 64 + c0] =
                    make_float2(acc[mt][nt][2 * pr + 0], acc[mt][nt][2 * pr + 1]);
            }
        }
}

// ---------------- combine splits: normalize + bias + ELU ----------------
template<int S, int HH>
__global__ void k_comb(const float* __restrict__ part, const float* __restrict__ rsum,
                       const float* __restrict__ bias, float* __restrict__ out) {
    const int ldn = HH * 64;
    int idx = blockIdx.x * 256 + threadIdx.x;
    if (idx >= N * ldn) return;
    int n = idx / ldn, hc = idx % ldn, h = hc >> 6;
    float cs = 0.f, rs = 0.f;
#pragma unroll
    for (int s = 0; s < S; s++) {
        cs += part[((size_t)s * N + n) * ldn + hc];
        rs += rsum[((size_t)s * HH + h) * N + n];
    }
    float v = cs / rs + bias[hc];
    out[idx] = v > 0.f ? v : (expf(v) - 1.f);
}

// ---------------- segment-mean pool + final linear ----------------
__global__ void k_pool(const float* __restrict__ o2, const int* __restrict__ batch,
                       const float* __restrict__ Wl, const float* __restrict__ bl,
                       float* __restrict__ out) {
    int g = blockIdx.x;
    __shared__ float acc[4][64];
    __shared__ float cnts[4];
    int tid = threadIdx.x, q = tid >> 6, c = tid & 63;
    float s = 0.f, cn = 0.f;
    for (int n = q; n < N; n += 4) {
        if (batch[n] == g) { s += o2[(size_t)n * 64 + c]; cn += 1.f; }
    }
    acc[q][c] = s;
    if (c == 0) cnts[q] = cn;
    __syncthreads();
    if (q == 0) {
        float tot = acc[0][c] + acc[1][c] + acc[2][c] + acc[3][c];
        float cc = cnts[0] + cnts[1] + cnts[2] + cnts[3];
        acc[0][c] = tot / fmaxf(cc, 1.f);
    }
    __syncthreads();
    if (tid < OUTF) {
        float s2 = bl[tid];
        for (int c2 = 0; c2 < 64; c2++) s2 += acc[0][c2] * Wl[c2 * OUTF + tid];
        out[g * OUTF + tid] = s2;
    }
}

// ---------------- host ----------------
extern "C" void kernel_launch(void* const* d_in, const int* in_sizes, int n_in,
                              void* d_out, int out_size) {
    const float* x        = (const float*)d_in[0];
    const float* attn     = (const float*)d_in[1];
    const int*   batch    = (const int*)d_in[2];
    const float* w_agg    = (const float*)d_in[3];
    const float* b_agg    = (const float*)d_in[4];
    const float* W1       = (const float*)d_in[5];
    const float* att_src1 = (const float*)d_in[6];
    const float* att_dst1 = (const float*)d_in[7];
    const float* We1      = (const float*)d_in[8];
    const float* att_e1   = (const float*)d_in[9];
    const float* bias1    = (const float*)d_in[10];
    const float* W2       = (const float*)d_in[11];
    const float* att_src2 = (const float*)d_in[12];
    const float* att_dst2 = (const float*)d_in[13];
    const float* We2      = (const float*)d_in[14];
    const float* att_e2   = (const float*)d_in[15];
    const float* bias2    = (const float*)d_in[16];
    const float* W_lin    = (const float*)d_in[17];
    const float* b_lin    = (const float*)d_in[18];

    float* out  = (float*)d_out;
    float* edge = out + (out_size - NN);

    float *csum, *ccnt, *meanp, *wep, *hf1t, *hf2t, *asp, *adp, *partp, *rsump, *o1p, *o2p;
    cudaGetSymbolAddress((void**)&csum,  g_csum);
    cudaGetSymbolAddress((void**)&ccnt,  g_ccnt);
    cudaGetSymbolAddress((void**)&meanp, g_mean);
    cudaGetSymbolAddress((void**)&wep,   g_we);
    cudaGetSymbolAddress((void**)&hf1t,  g_hf1t);
    cudaGetSymbolAddress((void**)&hf2t,  g_hf2t);
    cudaGetSymbolAddress((void**)&asp,   g_as);
    cudaGetSymbolAddress((void**)&adp,   g_ad);
    cudaGetSymbolAddress((void**)&partp, g_part);
    cudaGetSymbolAddress((void**)&rsump, g_rsum);
    cudaGetSymbolAddress((void**)&o1p,   g_o1);
    cudaGetSymbolAddress((void**)&o2p,   g_o2);

    // dynamic smem sizes: AsT(8704) + Bs(4608) + Es(12288) + s_as(KR) + rred(1024) floats
    const int SM1 = (8704 + 4608 + 12288 + 256 + 1024) * 4;   // S=8  -> KR=256
    const int SM2 = (8704 + 4608 + 12288 + 128 + 1024) * 4;   // S=16 -> KR=128
    cudaFuncSetAttribute(k_fattn<4, 8>,  cudaFuncAttributeMaxDynamicSharedMemorySize, SM1);
    cudaFuncSetAttribute(k_fattn<1, 16>, cudaFuncAttributeMaxDynamicSharedMemorySize, SM2);

    // edge + column stats (fused)
    k_aggT<<<dim3(32, 32), 256>>>(attn, w_agg, b_agg, edge, csum, ccnt);
    // features layer1 + attention dots
    k_gemm<64><<<dim3(32, 4), 256>>>(x, W1, hf1t, 128, 256, 256,
                                     att_src1, att_dst1, asp, adp);
    // means + edge-weight scalars
    k_mean<<<9, 256>>>(csum, ccnt, meanp, We1, att_e1, We2, att_e2, wep);

    // ---- GAT layer 1 (H=4, S=8, 128-dst tiles, h-major grid) ----
    k_fattn<4, 8><<<dim3(4, 16, 8), 256, SM1>>>(edge, meanp, asp, adp, wep, 0, hf1t, partp, rsump);
    k_comb<8, 4><<<N * 256 / 256, 256>>>(partp, rsump, bias1, o1p);

    // ---- GAT layer 2 (H=1, S=16) ----
    k_gemm<32><<<dim3(64, 1), 256>>>(o1p, W2, hf2t, 256, 64, 64,
                                     att_src2, att_dst2, asp, adp);
    k_fattn<1, 16><<<dim3(1, 16, 16), 256, SM2>>>(edge, meanp, asp, adp, wep, 4, hf2t, partp, rsump);
    k_comb<16, 1><<<N * 64 / 256, 256>>>(partp, rsump, bias2, o2p);

    // ---- pool + final linear ----
    k_pool<<<NG, 256>>>(o2p, batch, W_lin, b_lin, out);
}

// round 12
// speedup vs baseline: 1.0976x; 1.0696x over previous
#include <cuda_runtime.h>
#include <cuda_bf16.h>
#include <cstdint>
#include <math.h>

#define N 2048
#define NN (N*N)
#define K12 12
#define H1 4
#define NG 8
#define OUTF 10
#define KCH 32
#define LOG2E 1.4426950408889634f

// ---------------- scratch ----------------
__device__ float g_csum[32*N];
__device__ float g_ccnt[32*N];
__device__ float g_mean[N];
__device__ float g_we[8];
__device__ float g_hf1t[N*256];
__device__ float g_hf2t[N*64];
__device__ float g_as[H1*N];
__device__ float g_ad[H1*N];
__device__ float g_part[8*N*256];
__device__ float g_rsum[32*N];
__device__ float g_o1[N*256];
__device__ float g_o2[N*64];

__device__ __forceinline__ float to_tf32(float x) {
    unsigned int u;
    asm("cvt.rna.tf32.f32 %0, %1;" : "=r"(u) : "f"(x));
    return __uint_as_float(u);
}

// ---------------- 1: agg = w.attn + b ; edge = relu ; register-resident column stats ----------------
__global__ void __launch_bounds__(256) k_aggT(const float* __restrict__ attn,
                                              const float* __restrict__ w,
                                              const float* __restrict__ b,
                                              float* __restrict__ edge,
                                              float* __restrict__ csum,
                                              float* __restrict__ ccnt) {
    __shared__ float rs[16][64], rc[16][64];
    int bx = blockIdx.x * 64, by = blockIdx.y * 64;
    int tid = threadIdx.x;
    int tx = tid & 15, ty = tid >> 4;
    float wv[K12];
#pragma unroll
    for (int k = 0; k < K12; k++) wv[k] = w[k];
    float bb = b[0];
    float cs[4] = {0.f, 0.f, 0.f, 0.f}, cc[4] = {0.f, 0.f, 0.f, 0.f};
#pragma unroll
    for (int rr = 0; rr < 4; rr++) {
        int row = rr * 16 + ty;
        float4 acc = make_float4(bb, bb, bb, bb);
#pragma unroll
        for (int k = 0; k < K12; k++) {
            float4 v = *(const float4*)(attn + (size_t)k * NN + (size_t)(by + row) * N + bx + tx * 4);
            acc.x += wv[k] * v.x; acc.y += wv[k] * v.y;
            acc.z += wv[k] * v.z; acc.w += wv[k] * v.w;
        }
        acc.x = acc.x > 0.f ? acc.x : 0.f;
        acc.y = acc.y > 0.f ? acc.y : 0.f;
        acc.z = acc.z > 0.f ? acc.z : 0.f;
        acc.w = acc.w > 0.f ? acc.w : 0.f;
        *(float4*)(edge + (size_t)(by + row) * N + bx + tx * 4) = acc;
        int grow = by + row;
        float av[4] = {acc.x, acc.y, acc.z, acc.w};
#pragma unroll
        for (int q = 0; q < 4; q++) {
            if (av[q] > 0.f && grow != bx + tx * 4 + q) { cs[q] += av[q]; cc[q] += 1.f; }
        }
    }
    *(float4*)&rs[ty][tx * 4] = make_float4(cs[0], cs[1], cs[2], cs[3]);
    *(float4*)&rc[ty][tx * 4] = make_float4(cc[0], cc[1], cc[2], cc[3]);
    __syncthreads();
    if (tid < 64) {
        float s = 0.f, c = 0.f;
#pragma unroll
        for (int g = 0; g < 16; g++) { s += rs[g][tid]; c += rc[g][tid]; }
        csum[blockIdx.y * N + bx + tid] = s;
        ccnt[blockIdx.y * N + bx + tid] = c;
    }
}

// ---------------- 2: means + per-head edge weights ----------------
__global__ void k_mean(const float* __restrict__ cs, const float* __restrict__ cc,
                       float* __restrict__ mean,
                       const float* __restrict__ We1, const float* __restrict__ ae1,
                       const float* __restrict__ We2, const float* __restrict__ ae2,
                       float* __restrict__ we) {
    int j = blockIdx.x * 256 + threadIdx.x;
    if (j < N) {
        float s = 0.f, c = 0.f;
        for (int b2 = 0; b2 < 32; b2++) { s += cs[b2 * N + j]; c += cc[b2 * N + j]; }
        mean[j] = c > 0.f ? s / c : 0.f;
    }
    if (blockIdx.x == 8) {
        int t = threadIdx.x;
        if (t < 4) {
            float s = 0.f;
            for (int c = 0; c < 64; c++) s += We1[t * 64 + c] * ae1[t * 64 + c];
            we[t] = s;
        } else if (t == 4) {
            float s = 0.f;
            for (int c = 0; c < 64; c++) s += We2[c] * ae2[c];
            we[4] = s;
        }
    }
}

// ---------------- feature GEMM + attention-dot epilogue + tf32 output ----------------
template<int TM>
__global__ void __launch_bounds__(256) k_gemm(const float* __restrict__ A,
        const float* __restrict__ B, float* __restrict__ Ct, int K, int ldb, int ldn,
        const float* __restrict__ asrc, const float* __restrict__ adst,
        float* __restrict__ oas, float* __restrict__ oad) {
    constexpr int R = TM / 16;
    __shared__ float As2[16][TM + 1];
    __shared__ float Bs2[16][64];
    int h = blockIdx.y;
    int m0 = blockIdx.x * TM, n0 = h * 64;
    int tid = threadIdx.x;
    int tx = tid & 15, ty = tid >> 4;
    float acc[R][4];
#pragma unroll
    for (int r = 0; r < R; r++)
#pragma unroll
        for (int c = 0; c < 4; c++) acc[r][c] = 0.f;
    for (int k0 = 0; k0 < K; k0 += 16) {
#pragma unroll
        for (int l = 0; l < R; l++) {
            int e = l * 256 + tid;
            As2[e & 15][e >> 4] = A[(size_t)(m0 + (e >> 4)) * K + k0 + (e & 15)];
        }
#pragma unroll
        for (int l = 0; l < 4; l++) {
            int e = l * 256 + tid;
            Bs2[e >> 6][e & 63] = B[(size_t)(k0 + (e >> 6)) * ldb + n0 + (e & 63)];
        }
        __syncthreads();
#pragma unroll
        for (int kk = 0; kk < 16; kk++) {
            float a[R], bb[4];
#pragma unroll
            for (int r = 0; r < R; r++) a[r] = As2[kk][ty * R + r];
#pragma unroll
            for (int c = 0; c < 4; c++) bb[c] = Bs2[kk][tx * 4 + c];
#pragma unroll
            for (int r = 0; r < R; r++)
#pragma unroll
                for (int c = 0; c < 4; c++) acc[r][c] += a[r] * bb[c];
        }
        __syncthreads();
    }
    int lane = tid & 31;
    float asv[4], adv[4];
#pragma unroll
    for (int c = 0; c < 4; c++) {
        asv[c] = asrc[h * 64 + tx * 4 + c];
        adv[c] = adst[h * 64 + tx * 4 + c];
    }
#pragma unroll
    for (int r = 0; r < R; r++) {
        int row = m0 + ty * R + r;
        float ds = 0.f, dd = 0.f;
#pragma unroll
        for (int c = 0; c < 4; c++) {
            float v = acc[r][c];
            Ct[(size_t)row * ldn + n0 + tx * 4 + c] = to_tf32(v);
            ds += v * asv[c];
            dd += v * adv[c];
        }
#pragma unroll
        for (int m = 1; m < 16; m <<= 1) {
            ds += __shfl_xor_sync(0xffffffffu, ds, m);
            dd += __shfl_xor_sync(0xffffffffu, dd, m);
        }
        if ((lane & 15) == 0) { oas[h * N + row] = ds; oad[h * N + row] = dd; }
    }
}

// ---------------- fused logits + softmax + tf32 MMA (h-major grid, single-wave splits) ----------------
template<int H, int S>
__global__ void __launch_bounds__(256, 2) k_fattn(const float* __restrict__ edge,
        const float* __restrict__ mean, const float* __restrict__ as_,
        const float* __restrict__ ad_, const float* __restrict__ wep, int woff,
        const float* __restrict__ Bf, float* __restrict__ part, float* __restrict__ rsum) {
    constexpr int KR = N / S;
    constexpr int CH = KR / KCH;
    const int ldn = H * 64;
    __shared__ float AsT[2][KCH][136];
    __shared__ float Bs[2][KCH][72];
    __shared__ float s_as[KR];
    __shared__ float rred[8][32][4];
    int tid = threadIdx.x;
    int h = blockIdx.x, m0 = blockIdx.y * 128, s = blockIdx.z;
    int kb = s * KR;
    for (int idx = tid; idx < KR; idx += 256) s_as[idx] = as_[h * N + kb + idx] * LOG2E;
    int jq = tid & 31, ig = tid >> 5;
    float adj[4], me[4];
#pragma unroll
    for (int q = 0; q < 4; q++) {
        adj[q] = ad_[h * N + m0 + jq * 4 + q] * LOG2E;
        me[q]  = mean[m0 + jq * 4 + q];
    }
    float wev = wep[woff + h] * LOG2E;
    int brow = tid >> 3, bc8 = tid & 7;
    int wid = tid >> 5, lane = tid & 31;
    int wm = wid >> 1, wn = wid & 1, gid = lane >> 2, tig = lane & 3;
    float acc[2][4][4];
#pragma unroll
    for (int mt = 0; mt < 2; mt++)
#pragma unroll
        for (int nt = 0; nt < 4; nt++)
#pragma unroll
            for (int q = 0; q < 4; q++) acc[mt][nt][q] = 0.f;
    float racc[4] = {0.f, 0.f, 0.f, 0.f};
    float4 ev4[4];
    float4 bv0, bv1;
#pragma unroll
    for (int b = 0; b < 4; b++)
        ev4[b] = *(const float4*)(edge + (size_t)(kb + ig + 8 * b) * N + m0 + jq * 4);
    bv0 = *(const float4*)(Bf + (size_t)(kb + brow) * ldn + h * 64 + bc8 * 8);
    bv1 = *(const float4*)(Bf + (size_t)(kb + brow) * ldn + h * 64 + bc8 * 8 + 4);
    __syncthreads();   // s_as ready

#pragma unroll 2
    for (int c = 0; c < CH; c++) {
        int buf = c & 1;
        int kc = kb + c * KCH;
#pragma unroll
        for (int b = 0; b < 4; b++) {
            int il = ig + 8 * b;
            int srcg = kc + il;
            float p4[4];
            float evq[4] = {ev4[b].x, ev4[b].y, ev4[b].z, ev4[b].w};
            float sa = s_as[c * KCH + il];
#pragma unroll
            for (int q = 0; q < 4; q++) {
                bool diag = (srcg == m0 + jq * 4 + q);
                float e = diag ? me[q] : evq[q];
                bool on = diag || (evq[q] > 0.f);
                float v = sa + adj[q] + e * wev;
                v = fmaxf(v, 0.2f * v);
                float p;
                asm("ex2.approx.f32 %0, %1;" : "=f"(p) : "f"(v));
                p = on ? to_tf32(p) : 0.f;
                p4[q] = p;
                racc[q] += p;
            }
            *(float4*)&AsT[buf][il][jq * 4] = make_float4(p4[0], p4[1], p4[2], p4[3]);
        }
        *(float4*)&Bs[buf][brow][bc8 * 8]     = bv0;
        *(float4*)&Bs[buf][brow][bc8 * 8 + 4] = bv1;
        __syncthreads();
        if (c + 1 < CH) {
            int kn = kc + KCH;
#pragma unroll
            for (int b = 0; b < 4; b++)
                ev4[b] = *(const float4*)(edge + (size_t)(kn + ig + 8 * b) * N + m0 + jq * 4);
            bv0 = *(const float4*)(Bf + (size_t)(kn + brow) * ldn + h * 64 + bc8 * 8);
            bv1 = *(const float4*)(Bf + (size_t)(kn + brow) * ldn + h * 64 + bc8 * 8 + 4);
        }
#pragma unroll
        for (int kk = 0; kk < 4; kk++) {
            float a[2][4], bq[4][2];
#pragma unroll
            for (int mt = 0; mt < 2; mt++) {
                int r0 = wm * 32 + mt * 16 + gid;
                a[mt][0] = AsT[buf][kk * 8 + tig][r0];
                a[mt][1] = AsT[buf][kk * 8 + tig][r0 + 8];
                a[mt][2] = AsT[buf][kk * 8 + tig + 4][r0];
                a[mt][3] = AsT[buf][kk * 8 + tig + 4][r0 + 8];
            }
#pragma unroll
            for (int nt = 0; nt < 4; nt++) {
                int c0 = wn * 32 + nt * 8 + gid;
                bq[nt][0] = Bs[buf][kk * 8 + tig][c0];
                bq[nt][1] = Bs[buf][kk * 8 + tig + 4][c0];
            }
#pragma unroll
            for (int mt = 0; mt < 2; mt++)
#pragma unroll
                for (int nt = 0; nt < 4; nt++)
                    asm volatile("mma.sync.aligned.m16n8k8.row.col.f32.tf32.tf32.f32 "
                                 "{%0,%1,%2,%3}, {%4,%5,%6,%7}, {%8,%9}, {%0,%1,%2,%3};"
                                 : "+f"(acc[mt][nt][0]), "+f"(acc[mt][nt][1]),
                                   "+f"(acc[mt][nt][2]), "+f"(acc[mt][nt][3])
                                 : "r"(__float_as_uint(a[mt][0])), "r"(__float_as_uint(a[mt][1])),
                                   "r"(__float_as_uint(a[mt][2])), "r"(__float_as_uint(a[mt][3])),
                                   "r"(__float_as_uint(bq[nt][0])), "r"(__float_as_uint(bq[nt][1])));
        }
    }

    *(float4*)&rred[ig][jq][0] = make_float4(racc[0], racc[1], racc[2], racc[3]);
    __syncthreads();
    if (tid < 128) {
        float ssum = 0.f;
#pragma unroll
        for (int g = 0; g < 8; g++) ssum += rred[g][tid >> 2][tid & 3];
        rsum[((size_t)s * H + h) * N + m0 + tid] = ssum;
    }
#pragma unroll
    for (int mt = 0; mt < 2; mt++)
#pragma unroll
        for (int nt = 0; nt < 4; nt++) {
            int c0 = wn * 32 + nt * 8 + tig * 2;
#pragma unroll
            for (int pr = 0; pr < 2; pr++) {
                int r = m0 + wm * 32 + mt * 16 + gid + pr * 8;
                *(float2*)&part[((size_t)s * N + r) * ldn + h * 64 + c0] =
                    make_float2(acc[mt][nt][2 * pr + 0], acc[mt][nt][2 * pr + 1]);
            }
        }
}

// ---------------- combine splits: normalize + bias + ELU ----------------
template<int S, int HH>
__global__ void k_comb(const float* __restrict__ part, const float* __restrict__ rsum,
                       const float* __restrict__ bias, float* __restrict__ out) {
    const int ldn = HH * 64;
    int idx = blockIdx.x * 256 + threadIdx.x;
    if (idx >= N * ldn) return;
    int n = idx / ldn, hc = idx % ldn, h = hc >> 6;
    float cs = 0.f, rs = 0.f;
#pragma unroll
    for (int s = 0; s < S; s++) {
        cs += part[((size_t)s * N + n) * ldn + hc];
        rs += rsum[((size_t)s * HH + h) * N + n];
    }
    float v = cs / rs + bias[hc];
    out[idx] = v > 0.f ? v : (expf(v) - 1.f);
}

// ---------------- segment-mean pool + final linear ----------------
__global__ void k_pool(const float* __restrict__ o2, const int* __restrict__ batch,
                       const float* __restrict__ Wl, const float* __restrict__ bl,
                       float* __restrict__ out) {
    int g = blockIdx.x;
    __shared__ float acc[4][64];
    __shared__ float cnts[4];
    int tid = threadIdx.x, q = tid >> 6, c = tid & 63;
    float s = 0.f, cn = 0.f;
    for (int n = q; n < N; n += 4) {
        if (batch[n] == g) { s += o2[(size_t)n * 64 + c]; cn += 1.f; }
    }
    acc[q][c] = s;
    if (c == 0) cnts[q] = cn;
    __syncthreads();
    if (q == 0) {
        float tot = acc[0][c] + acc[1][c] + acc[2][c] + acc[3][c];
        float cc = cnts[0] + cnts[1] + cnts[2] + cnts[3];
        acc[0][c] = tot / fmaxf(cc, 1.f);
    }
    __syncthreads();
    if (tid < OUTF) {
        float s2 = bl[tid];
        for (int c2 = 0; c2 < 64; c2++) s2 += acc[0][c2] * Wl[c2 * OUTF + tid];
        out[g * OUTF + tid] = s2;
    }
}

// ---------------- host ----------------
extern "C" void kernel_launch(void* const* d_in, const int* in_sizes, int n_in,
                              void* d_out, int out_size) {
    const float* x        = (const float*)d_in[0];
    const float* attn     = (const float*)d_in[1];
    const int*   batch    = (const int*)d_in[2];
    const float* w_agg    = (const float*)d_in[3];
    const float* b_agg    = (const float*)d_in[4];
    const float* W1       = (const float*)d_in[5];
    const float* att_src1 = (const float*)d_in[6];
    const float* att_dst1 = (const float*)d_in[7];
    const float* We1      = (const float*)d_in[8];
    const float* att_e1   = (const float*)d_in[9];
    const float* bias1    = (const float*)d_in[10];
    const float* W2       = (const float*)d_in[11];
    const float* att_src2 = (const float*)d_in[12];
    const float* att_dst2 = (const float*)d_in[13];
    const float* We2      = (const float*)d_in[14];
    const float* att_e2   = (const float*)d_in[15];
    const float* bias2    = (const float*)d_in[16];
    const float* W_lin    = (const float*)d_in[17];
    const float* b_lin    = (const float*)d_in[18];

    float* out  = (float*)d_out;
    float* edge = out + (out_size - NN);

    float *csum, *ccnt, *meanp, *wep, *hf1t, *hf2t, *asp, *adp, *partp, *rsump, *o1p, *o2p;
    cudaGetSymbolAddress((void**)&csum,  g_csum);
    cudaGetSymbolAddress((void**)&ccnt,  g_ccnt);
    cudaGetSymbolAddress((void**)&meanp, g_mean);
    cudaGetSymbolAddress((void**)&wep,   g_we);
    cudaGetSymbolAddress((void**)&hf1t,  g_hf1t);
    cudaGetSymbolAddress((void**)&hf2t,  g_hf2t);
    cudaGetSymbolAddress((void**)&asp,   g_as);
    cudaGetSymbolAddress((void**)&adp,   g_ad);
    cudaGetSymbolAddress((void**)&partp, g_part);
    cudaGetSymbolAddress((void**)&rsump, g_rsum);
    cudaGetSymbolAddress((void**)&o1p,   g_o1);
    cudaGetSymbolAddress((void**)&o2p,   g_o2);

    // edge + column stats (fused)
    k_aggT<<<dim3(32, 32), 256>>>(attn, w_agg, b_agg, edge, csum, ccnt);
    // features layer1 + attention dots (independent of aggT)
    k_gemm<64><<<dim3(32, 4), 256>>>(x, W1, hf1t, 128, 256, 256,
                                     att_src1, att_dst1, asp, adp);
    // means + edge-weight scalars
    k_mean<<<9, 256>>>(csum, ccnt, meanp, We1, att_e1, We2, att_e2, wep);

    // ---- GAT layer 1 (H=4, S=4 -> 256 CTAs, single wave) ----
    k_fattn<4, 4><<<dim3(4, 16, 4), 256>>>(edge, meanp, asp, adp, wep, 0, hf1t, partp, rsump);
    k_comb<4, 4><<<N * 256 / 256, 256>>>(partp, rsump, bias1, o1p);

    // ---- GAT layer 2 (H=1, S=8 -> 128 CTAs, single wave) ----
    k_gemm<32><<<dim3(64, 1), 256>>>(o1p, W2, hf2t, 256, 64, 64,
                                     att_src2, att_dst2, asp, adp);
    k_fattn<1, 8><<<dim3(1, 16, 8), 256>>>(edge, meanp, asp, adp, wep, 4, hf2t, partp, rsump);
    k_comb<8, 1><<<N * 64 / 256, 256>>>(partp, rsump, bias2, o2p);

    // ---- pool + final linear ----
    k_pool<<<NG, 256>>>(o2p, batch, W_lin, b_lin, out);
}